// round 17
// baseline (speedup 1.0000x reference)
#include <cuda_runtime.h>
#include <math.h>
#include <stdint.h>

// ---------------- problem constants ----------------
#define CB   32
#define CN   4096
#define CD   256
#define CH   4
#define CHD  64
#define CS   16
#define CGH  128
#define CMH  1024
#define CT   (CB*CN)      // 131072 tokens
#define CBS  (CB*CS)      // 512 slot rows
#define CV8  (CT*8)       // 1048576 grid-enc vectors

// ---------------- scratch (device globals) ----------------
__device__ float g_x    [CT*CD];        // LN'd features
__device__ float g_pre  [CT*512];       // LN'd kpre|vpre (viewed as CV8 x 64)
__device__ float g_kv   [CT*512];       // final k|v
__device__ float g_wkv  [CD*512];       // [Wk|Wv]
__device__ float g_wog  [CD*768];       // Wo @ gru_Wi  (folded)
__device__ float g_slots[CBS*CD];
__device__ float g_sn   [CBS*CD];       // LN'd slots
__device__ float g_q    [CBS*CD];
__device__ float g_part [4096*16*64];   // attention partials [bh*32+p][16][64]
__device__ float g_psum [4096*16];      // rowsum partials
__device__ float g_upd  [CBS*CD];
__device__ float g_gi   [CBS*3*CD];
__device__ float g_gh   [CBS*3*CD];
__device__ float g_mlp1 [CBS*CMH];

// ---------------- tf32 MMA helpers ----------------
__device__ __forceinline__ uint32_t f2tf(float f) {
    uint32_t u;
    asm("cvt.rna.tf32.f32 %0, %1;" : "=r"(u) : "f"(f));
    return u;
}
__device__ __forceinline__ void mma_tf32(float* d, const uint32_t* a, const uint32_t* b) {
    asm volatile(
        "mma.sync.aligned.m16n8k8.row.col.f32.tf32.tf32.f32 "
        "{%0,%1,%2,%3}, {%4,%5,%6,%7}, {%8,%9}, {%0,%1,%2,%3};\n"
        : "+f"(d[0]), "+f"(d[1]), "+f"(d[2]), "+f"(d[3])
        : "r"(a[0]), "r"(a[1]), "r"(a[2]), "r"(a[3]), "r"(b[0]), "r"(b[1]));
}

// ---------------- small utility kernels ----------------
__global__ void k_copy(const float* __restrict__ src, float* __restrict__ dst, int n) {
    int i = blockIdx.x * 256 + threadIdx.x;
    if (i < n) dst[i] = src[i];
}
__global__ void k_build_wkv(const float* __restrict__ Wk, const float* __restrict__ Wv,
                            float* __restrict__ Wkv) {
    int i = blockIdx.x * 256 + threadIdx.x;   // < 256*512
    int d = i >> 9, j = i & 511;
    Wkv[i] = (j < 256) ? Wk[d * 256 + j] : Wv[d * 256 + (j - 256)];
}

// LayerNorm over 256 features; ONE WARP PER ROW, 8 rows per block.
// float2 loads (instride=258 leaves odd rows 8B-aligned only), shfl reduce.
__global__ __launch_bounds__(256) void k_lnrow(
    const float* __restrict__ in, int instride,
    const float* __restrict__ s, const float* __restrict__ bb,
    float* __restrict__ out)
{
    int row = blockIdx.x * 8 + (threadIdx.x >> 5);
    int lane = threadIdx.x & 31;
    const float* ip = in + (size_t)row * instride + lane * 8;
    float2 v[4];
    #pragma unroll
    for (int i = 0; i < 4; i++) v[i] = *reinterpret_cast<const float2*>(ip + i * 2);
    float sum = 0.f, sq = 0.f;
    #pragma unroll
    for (int i = 0; i < 4; i++) {
        sum += v[i].x + v[i].y;
        sq  += v[i].x * v[i].x + v[i].y * v[i].y;
    }
    #pragma unroll
    for (int o = 16; o > 0; o >>= 1) {
        sum += __shfl_xor_sync(~0u, sum, o);
        sq  += __shfl_xor_sync(~0u, sq, o);
    }
    float m  = sum * (1.f / 256.f);
    float rs = rsqrtf(sq * (1.f / 256.f) - m * m + 1e-6f);
    float* op = out + (size_t)row * 256 + lane * 8;
    #pragma unroll
    for (int i = 0; i < 4; i++) {
        float2 sv = *reinterpret_cast<const float2*>(s + lane * 8 + i * 2);
        float2 bv = *reinterpret_cast<const float2*>(bb + lane * 8 + i * 2);
        float2 o;
        o.x = (v[i].x - m) * rs * sv.x + bv.x;
        o.y = (v[i].y - m) * rs * sv.y + bv.y;
        *reinterpret_cast<float2*>(op + i * 2) = o;
    }
}

// ============================================================================
// k_kvpre: pre = LN64( x(131072x256) @ Wkv(256x512) + positional )
// tf32 MMA, block tile 128x128, 8 warps (warp tile 32x64), BK=32.
// ============================================================================
__global__ __launch_bounds__(256) void k_kvpre(
    const float* __restrict__ A, const float* __restrict__ Bm, float* __restrict__ C,
    const float* __restrict__ gridsrc, const float* __restrict__ Wp,
    const float* __restrict__ ges, const float* __restrict__ geb)
{
    __shared__ uint32_t As[128 * 36];
    __shared__ uint32_t Bs[32 * 132];
    int tid = threadIdx.x;
    int lane = tid & 31;
    int g = lane >> 2, t = lane & 3;
    int wid = tid >> 5;
    int wm = wid & 3, wn = wid >> 2;
    int row0 = blockIdx.y * 128, col0 = blockIdx.x * 128;

    float acc[2][8][4];
    #pragma unroll
    for (int mt = 0; mt < 2; mt++)
        #pragma unroll
        for (int nt = 0; nt < 8; nt++)
            #pragma unroll
            for (int c = 0; c < 4; c++) acc[mt][nt][c] = 0.f;

    for (int kt = 0; kt < 256; kt += 32) {
        #pragma unroll
        for (int it = 0; it < 4; it++) {
            int f4 = tid + it * 256;
            int m = f4 >> 3, k4 = (f4 & 7) * 4;
            float4 v = *reinterpret_cast<const float4*>(A + (size_t)(row0 + m) * 256 + kt + k4);
            *reinterpret_cast<uint4*>(&As[m * 36 + k4]) =
                make_uint4(f2tf(v.x), f2tf(v.y), f2tf(v.z), f2tf(v.w));
        }
        #pragma unroll
        for (int it = 0; it < 4; it++) {
            int f4 = tid + it * 256;
            int k = f4 >> 5, n4 = (f4 & 31) * 4;
            float4 v = *reinterpret_cast<const float4*>(Bm + (size_t)(kt + k) * 512 + col0 + n4);
            *reinterpret_cast<uint4*>(&Bs[k * 132 + n4]) =
                make_uint4(f2tf(v.x), f2tf(v.y), f2tf(v.z), f2tf(v.w));
        }
        __syncthreads();
        #pragma unroll
        for (int k8 = 0; k8 < 4; k8++) {
            int k0 = k8 * 8;
            uint32_t a[2][4], b[8][2];
            #pragma unroll
            for (int mt = 0; mt < 2; mt++) {
                int m = wm * 32 + mt * 16;
                a[mt][0] = As[(m + g) * 36 + k0 + t];
                a[mt][1] = As[(m + 8 + g) * 36 + k0 + t];
                a[mt][2] = As[(m + g) * 36 + k0 + t + 4];
                a[mt][3] = As[(m + 8 + g) * 36 + k0 + t + 4];
            }
            #pragma unroll
            for (int nt = 0; nt < 8; nt++) {
                int n = wn * 64 + nt * 8 + g;
                b[nt][0] = Bs[(k0 + t) * 132 + n];
                b[nt][1] = Bs[(k0 + t + 4) * 132 + n];
            }
            #pragma unroll
            for (int mt = 0; mt < 2; mt++)
                #pragma unroll
                for (int nt = 0; nt < 8; nt++)
                    mma_tf32(acc[mt][nt], a[mt], b[nt]);
        }
        __syncthreads();
    }

    #pragma unroll
    for (int mt = 0; mt < 2; mt++) {
        int r0 = row0 + wm * 32 + mt * 16 + g;
        int r1 = r0 + 8;
        float p0a = gridsrc[(size_t)r0 * 258 + 256], p1a = gridsrc[(size_t)r0 * 258 + 257];
        float p0b = gridsrc[(size_t)r1 * 258 + 256], p1b = gridsrc[(size_t)r1 * 258 + 257];
        float s0 = 0.f, q0 = 0.f, s1 = 0.f, q1 = 0.f;
        #pragma unroll
        for (int nt = 0; nt < 8; nt++) {
            int col = col0 + wn * 64 + nt * 8 + t * 2;
            int jm = col & 255;
            float w00 = Wp[jm],       w01 = Wp[jm + 1];
            float w10 = Wp[256 + jm], w11 = Wp[257 + jm];
            float* c = acc[mt][nt];
            c[0] += p0a * w00 + p1a * w10;
            c[1] += p0a * w01 + p1a * w11;
            c[2] += p0b * w00 + p1b * w10;
            c[3] += p0b * w01 + p1b * w11;
            s0 += c[0] + c[1]; q0 += c[0] * c[0] + c[1] * c[1];
            s1 += c[2] + c[3]; q1 += c[2] * c[2] + c[3] * c[3];
        }
        #pragma unroll
        for (int o = 1; o <= 2; o <<= 1) {
            s0 += __shfl_xor_sync(~0u, s0, o);
            q0 += __shfl_xor_sync(~0u, q0, o);
            s1 += __shfl_xor_sync(~0u, s1, o);
            q1 += __shfl_xor_sync(~0u, q1, o);
        }
        float m0 = s0 * (1.f / 64.f), m1 = s1 * (1.f / 64.f);
        float rs0 = rsqrtf(q0 * (1.f / 64.f) - m0 * m0 + 1e-6f);
        float rs1 = rsqrtf(q1 * (1.f / 64.f) - m1 * m1 + 1e-6f);
        #pragma unroll
        for (int nt = 0; nt < 8; nt++) {
            int col = col0 + wn * 64 + nt * 8 + t * 2;
            int e = col & 63;
            float sc0 = ges[e], sc1 = ges[e + 1];
            float bb0 = geb[e], bb1 = geb[e + 1];
            float* c = acc[mt][nt];
            float2 o0 = make_float2((c[0] - m0) * rs0 * sc0 + bb0,
                                    (c[1] - m0) * rs0 * sc1 + bb1);
            float2 o1 = make_float2((c[2] - m1) * rs1 * sc0 + bb0,
                                    (c[3] - m1) * rs1 * sc1 + bb1);
            *reinterpret_cast<float2*>(C + (size_t)r0 * 512 + col) = o0;
            *reinterpret_cast<float2*>(C + (size_t)r1 * 512 + col) = o1;
        }
    }
}

// ============================================================================
// k_genc: fused grid-encoder MLP over 1M 64-wide vectors.
// ============================================================================
#define GENC_SMEM_BYTES (25856 * 4)
__global__ __launch_bounds__(256) void k_genc(
    const float* __restrict__ pre,
    const float* __restrict__ W1, const float* __restrict__ b1,
    const float* __restrict__ W2, const float* __restrict__ b2,
    float* __restrict__ out)
{
    extern __shared__ uint32_t sm[];
    uint32_t* IN  = sm;
    uint32_t* W1s = sm + 8704;
    uint32_t* HS  = sm;
    uint32_t* W2s = sm + 17152;

    int tid = threadIdx.x;
    int lane = tid & 31;
    int g = lane >> 2, t = lane & 3;
    int wid = tid >> 5;
    int wm = wid & 3, wn = wid >> 2;
    size_t v0 = (size_t)blockIdx.x * 128;

    #pragma unroll
    for (int it = 0; it < 8; it++) {
        int f4 = tid + it * 256;
        int m = f4 >> 4, k4 = (f4 & 15) * 4;
        float4 v = *reinterpret_cast<const float4*>(pre + (v0 + m) * 64 + k4);
        *reinterpret_cast<uint4*>(&IN[m * 68 + k4]) =
            make_uint4(f2tf(v.x), f2tf(v.y), f2tf(v.z), f2tf(v.w));
    }
    #pragma unroll
    for (int it = 0; it < 8; it++) {
        int f4 = tid + it * 256;
        int k = f4 >> 5, n4 = (f4 & 31) * 4;
        float4 v = *reinterpret_cast<const float4*>(W1 + (size_t)k * 128 + n4);
        *reinterpret_cast<uint4*>(&W1s[k * 132 + n4]) =
            make_uint4(f2tf(v.x), f2tf(v.y), f2tf(v.z), f2tf(v.w));
    }
    #pragma unroll
    for (int it = 0; it < 8; it++) {
        int f4 = tid + it * 256;
        int k = f4 >> 4, n4 = (f4 & 15) * 4;
        float4 v = *reinterpret_cast<const float4*>(W2 + (size_t)k * 64 + n4);
        *reinterpret_cast<uint4*>(&W2s[k * 68 + n4]) =
            make_uint4(f2tf(v.x), f2tf(v.y), f2tf(v.z), f2tf(v.w));
    }
    __syncthreads();

    float acc1[2][8][4];
    #pragma unroll
    for (int mt = 0; mt < 2; mt++)
        #pragma unroll
        for (int nt = 0; nt < 8; nt++)
            #pragma unroll
            for (int c = 0; c < 4; c++) acc1[mt][nt][c] = 0.f;

    #pragma unroll
    for (int k8 = 0; k8 < 8; k8++) {
        int k0 = k8 * 8;
        uint32_t a[2][4], b[8][2];
        #pragma unroll
        for (int mt = 0; mt < 2; mt++) {
            int m = wm * 32 + mt * 16;
            a[mt][0] = IN[(m + g) * 68 + k0 + t];
            a[mt][1] = IN[(m + 8 + g) * 68 + k0 + t];
            a[mt][2] = IN[(m + g) * 68 + k0 + t + 4];
            a[mt][3] = IN[(m + 8 + g) * 68 + k0 + t + 4];
        }
        #pragma unroll
        for (int nt = 0; nt < 8; nt++) {
            int n = wn * 64 + nt * 8 + g;
            b[nt][0] = W1s[(k0 + t) * 132 + n];
            b[nt][1] = W1s[(k0 + t + 4) * 132 + n];
        }
        #pragma unroll
        for (int mt = 0; mt < 2; mt++)
            #pragma unroll
            for (int nt = 0; nt < 8; nt++)
                mma_tf32(acc1[mt][nt], a[mt], b[nt]);
    }
    __syncthreads();

    #pragma unroll
    for (int mt = 0; mt < 2; mt++) {
        int r0 = wm * 32 + mt * 16 + g;
        int r1 = r0 + 8;
        #pragma unroll
        for (int nt = 0; nt < 8; nt++) {
            int col = wn * 64 + nt * 8 + t * 2;
            float bb0 = b1[col], bb1 = b1[col + 1];
            float* c = acc1[mt][nt];
            HS[r0 * 132 + col]     = f2tf(fmaxf(c[0] + bb0, 0.f));
            HS[r0 * 132 + col + 1] = f2tf(fmaxf(c[1] + bb1, 0.f));
            HS[r1 * 132 + col]     = f2tf(fmaxf(c[2] + bb0, 0.f));
            HS[r1 * 132 + col + 1] = f2tf(fmaxf(c[3] + bb1, 0.f));
        }
    }
    __syncthreads();

    float acc2[2][4][4];
    #pragma unroll
    for (int mt = 0; mt < 2; mt++)
        #pragma unroll
        for (int nt = 0; nt < 4; nt++)
            #pragma unroll
            for (int c = 0; c < 4; c++) acc2[mt][nt][c] = 0.f;

    #pragma unroll
    for (int k8 = 0; k8 < 16; k8++) {
        int k0 = k8 * 8;
        uint32_t a[2][4], b[4][2];
        #pragma unroll
        for (int mt = 0; mt < 2; mt++) {
            int m = wm * 32 + mt * 16;
            a[mt][0] = HS[(m + g) * 132 + k0 + t];
            a[mt][1] = HS[(m + 8 + g) * 132 + k0 + t];
            a[mt][2] = HS[(m + g) * 132 + k0 + t + 4];
            a[mt][3] = HS[(m + 8 + g) * 132 + k0 + t + 4];
        }
        #pragma unroll
        for (int nt = 0; nt < 4; nt++) {
            int n = wn * 32 + nt * 8 + g;
            b[nt][0] = W2s[(k0 + t) * 68 + n];
            b[nt][1] = W2s[(k0 + t + 4) * 68 + n];
        }
        #pragma unroll
        for (int mt = 0; mt < 2; mt++)
            #pragma unroll
            for (int nt = 0; nt < 4; nt++)
                mma_tf32(acc2[mt][nt], a[mt], b[nt]);
    }

    #pragma unroll
    for (int mt = 0; mt < 2; mt++) {
        int r0 = wm * 32 + mt * 16 + g;
        int r1 = r0 + 8;
        #pragma unroll
        for (int nt = 0; nt < 4; nt++) {
            int col = wn * 32 + nt * 8 + t * 2;
            float bb0 = b2[col], bb1 = b2[col + 1];
            float* c = acc2[mt][nt];
            *reinterpret_cast<float2*>(out + (v0 + r0) * 64 + col) =
                make_float2(c[0] + bb0, c[1] + bb1);
            *reinterpret_cast<float2*>(out + (v0 + r1) * 64 + col) =
                make_float2(c[2] + bb0, c[3] + bb1);
        }
    }
}

// ---------------- small SGEMM: BM=64 BN=64 BK=32, 256 thr, 4x4 microtile
// EPI: 0 plain, 1 +bias, 2 +bias+relu, 3 *scale, 4 res + acc + bias
template<int EPI>
__global__ __launch_bounds__(256) void k_small(
    const float* __restrict__ A, const float* __restrict__ Bm, float* __restrict__ C,
    int M, int Nc, int K,
    const float* __restrict__ bias, const float* __restrict__ res, float scale)
{
    const int BM = 64, BN = 64, BK = 32;
    __shared__ float As[BK][BM + 4];
    __shared__ float Bs[BK][BN];
    int tid = threadIdx.x;
    int tx = tid & 15, ty = tid >> 4;
    int row0 = blockIdx.y * BM;
    int col0 = blockIdx.x * BN;

    float acc[4][4];
    #pragma unroll
    for (int i = 0; i < 4; i++)
        #pragma unroll
        for (int j = 0; j < 4; j++) acc[i][j] = 0.f;

    for (int k0 = 0; k0 < K; k0 += BK) {
        #pragma unroll
        for (int it = 0; it < 2; ++it) {
            int f = tid + it * 256;
            int r = f >> 3, c = (f & 7) * 4;
            float4 v = *reinterpret_cast<const float4*>(A + (size_t)(row0 + r) * K + k0 + c);
            As[c + 0][r] = v.x; As[c + 1][r] = v.y;
            As[c + 2][r] = v.z; As[c + 3][r] = v.w;
        }
        #pragma unroll
        for (int it = 0; it < 2; ++it) {
            int f = tid + it * 256;
            int br = f >> 4, bc = (f & 15) * 4;
            *reinterpret_cast<float4*>(&Bs[br][bc]) =
                *reinterpret_cast<const float4*>(Bm + (size_t)(k0 + br) * Nc + col0 + bc);
        }
        __syncthreads();
        #pragma unroll
        for (int k = 0; k < BK; k++) {
            float4 b4 = *reinterpret_cast<const float4*>(&Bs[k][tx * 4]);
            float a0 = As[k][ty];
            float a1 = As[k][ty + 16];
            float a2 = As[k][ty + 32];
            float a3 = As[k][ty + 48];
            acc[0][0] = fmaf(a0, b4.x, acc[0][0]); acc[0][1] = fmaf(a0, b4.y, acc[0][1]);
            acc[0][2] = fmaf(a0, b4.z, acc[0][2]); acc[0][3] = fmaf(a0, b4.w, acc[0][3]);
            acc[1][0] = fmaf(a1, b4.x, acc[1][0]); acc[1][1] = fmaf(a1, b4.y, acc[1][1]);
            acc[1][2] = fmaf(a1, b4.z, acc[1][2]); acc[1][3] = fmaf(a1, b4.w, acc[1][3]);
            acc[2][0] = fmaf(a2, b4.x, acc[2][0]); acc[2][1] = fmaf(a2, b4.y, acc[2][1]);
            acc[2][2] = fmaf(a2, b4.z, acc[2][2]); acc[2][3] = fmaf(a2, b4.w, acc[2][3]);
            acc[3][0] = fmaf(a3, b4.x, acc[3][0]); acc[3][1] = fmaf(a3, b4.y, acc[3][1]);
            acc[3][2] = fmaf(a3, b4.z, acc[3][2]); acc[3][3] = fmaf(a3, b4.w, acc[3][3]);
        }
        __syncthreads();
    }

    int n = col0 + tx * 4;
    #pragma unroll
    for (int i = 0; i < 4; i++) {
        int m = row0 + ty + i * 16;
        float4 r;
        r.x = acc[i][0]; r.y = acc[i][1]; r.z = acc[i][2]; r.w = acc[i][3];
        if (EPI == 1) {
            float4 bv = *reinterpret_cast<const float4*>(bias + n);
            r.x += bv.x; r.y += bv.y; r.z += bv.z; r.w += bv.w;
        } else if (EPI == 2) {
            float4 bv = *reinterpret_cast<const float4*>(bias + n);
            r.x = fmaxf(r.x + bv.x, 0.f); r.y = fmaxf(r.y + bv.y, 0.f);
            r.z = fmaxf(r.z + bv.z, 0.f); r.w = fmaxf(r.w + bv.w, 0.f);
        } else if (EPI == 3) {
            r.x *= scale; r.y *= scale; r.z *= scale; r.w *= scale;
        } else if (EPI == 4) {
            float4 bv = *reinterpret_cast<const float4*>(bias + n);
            float4 rv = *reinterpret_cast<const float4*>(res + (size_t)m * Nc + n);
            r.x += bv.x + rv.x; r.y += bv.y + rv.y;
            r.z += bv.z + rv.z; r.w += bv.w + rv.w;
        }
        *reinterpret_cast<float4*>(C + (size_t)m * Nc + n) = r;
    }
}

// ---------------- fused attention: logits + slot-softmax + attn@v partials
// grid (8 seg, 128 bh), 256 threads. Each block owns 512 keys of one (b,h).
// Phase A: thread-per-key logits -> softmax -> smem sattn[s][key].
// Phase B: 4 key-groups x 64 dims accumulate attn@v + rowsums; write partials.
__global__ __launch_bounds__(256) void k_attn(
    const float* __restrict__ q,
    const float* __restrict__ kv,
    float* __restrict__ part,     // [4096][16][64]
    float* __restrict__ psum)     // [4096][16]
{
    int bh = blockIdx.y;
    int b = bh >> 2, h = bh & 3;
    int seg = blockIdx.x;
    int tid = threadIdx.x;

    __shared__ float qs[16][64];       // 4KB
    __shared__ float sattn[16][512];   // 32KB, s-major: conflict-free both phases

    {
        int row = tid >> 4, col = (tid & 15) * 4;
        float4 v = *reinterpret_cast<const float4*>(
            q + (size_t)(b * 16 + row) * 256 + h * 64 + col);
        *reinterpret_cast<float4*>(&qs[row][col]) = v;
    }
    __syncthreads();

    // ---- phase A: 2 keys per thread ----
    #pragma unroll
    for (int kt = 0; kt < 2; kt++) {
        int kl = tid + kt * 256;           // local key 0..511
        int kk = seg * 512 + kl;
        const float* kp = kv + (size_t)(b * 4096 + kk) * 512 + h * 64;
        float acc[16];
        #pragma unroll
        for (int s = 0; s < 16; s++) acc[s] = 0.f;
        #pragma unroll
        for (int ec = 0; ec < 16; ec++) {
            float4 k4 = *reinterpret_cast<const float4*>(kp + ec * 4);
            #pragma unroll
            for (int s = 0; s < 16; s++) {
                float4 q4 = *reinterpret_cast<const float4*>(&qs[s][ec * 4]);
                acc[s] = fmaf(k4.x, q4.x, acc[s]);
                acc[s] = fmaf(k4.y, q4.y, acc[s]);
                acc[s] = fmaf(k4.z, q4.z, acc[s]);
                acc[s] = fmaf(k4.w, q4.w, acc[s]);
            }
        }
        float mx = acc[0];
        #pragma unroll
        for (int s = 1; s < 16; s++) mx = fmaxf(mx, acc[s]);
        float tot = 0.f;
        #pragma unroll
        for (int s = 0; s < 16; s++) { acc[s] = expf(acc[s] - mx); tot += acc[s]; }
        float inv = 1.f / tot;
        #pragma unroll
        for (int s = 0; s < 16; s++) sattn[s][kl] = acc[s] * inv;
    }
    __syncthreads();

    // ---- phase B ----
    int e = tid & 63, kg = tid >> 6;       // 4 key groups
    float acc[16], rs[16];
    #pragma unroll
    for (int s = 0; s < 16; s++) { acc[s] = 0.f; rs[s] = 0.f; }

    const float* vbase = kv + (size_t)b * 4096 * 512 + 256 + h * 64 + e;
    #pragma unroll 4
    for (int j = 0; j < 128; j++) {
        int kl = j * 4 + kg;
        float vv = vbase[(size_t)(seg * 512 + kl) * 512];
        #pragma unroll
        for (int s = 0; s < 16; s++) {
            float a = sattn[s][kl];
            acc[s] = fmaf(a, vv, acc[s]);
            rs[s] += a;
        }
    }
    int pidx = bh * 32 + seg * 4 + kg;     // 0..4095
    float* pp = part + ((size_t)pidx * 16) * 64 + e;
    #pragma unroll
    for (int s = 0; s < 16; s++) pp[s * 64] = acc[s];
    if (e == 0) {
        #pragma unroll
        for (int s = 0; s < 16; s++) psum[pidx * 16 + s] = rs[s];
    }
}

// ---------------- attention reduce: upd = sum(partials) / (sum(rowsums)+eps)
__global__ __launch_bounds__(256) void k_attnred(
    const float* __restrict__ part, const float* __restrict__ psum,
    float* __restrict__ upd)
{
    int r = blockIdx.x;                 // slot row 0..511
    int b = r >> 4, sl = r & 15;
    int d = threadIdx.x;                // 0..255
    int h = d >> 6, e = d & 63;
    int bh = b * 4 + h;
    float t = 0.f, rt = 0.f;
    #pragma unroll
    for (int p = 0; p < 32; p++) {
        int idx = bh * 32 + p;
        t  += part[((size_t)idx * 16 + sl) * 64 + e];
        rt += psum[idx * 16 + sl];
    }
    upd[(size_t)r * 256 + d] = t / (rt + 1e-8f);
}

// ---------------- GRU update (elementwise), one block per slot row
__global__ __launch_bounds__(256) void k_gru(
    const float* __restrict__ gi, const float* __restrict__ gh,
    const float* __restrict__ bhn, float* __restrict__ slots)
{
    int r = blockIdx.x, d = threadIdx.x;
    size_t gb = (size_t)r * 768 + d;
    float ir = gi[gb], iz = gi[gb + 256], inn = gi[gb + 512];
    float hr = gh[gb], hz = gh[gb + 256], hn  = gh[gb + 512];
    float rr = 1.f / (1.f + expf(-(ir + hr)));
    float zz = 1.f / (1.f + expf(-(iz + hz)));
    float nn = tanhf(inn + rr * (hn + bhn[d]));
    size_t sb = (size_t)r * 256 + d;
    slots[sb] = (1.f - zz) * nn + zz * slots[sb];
}

// ---------------- host orchestration ----------------
extern "C" void kernel_launch(void* const* d_in, const int* in_sizes, int n_in,
                              void* d_out, int out_size)
{
    (void)in_sizes; (void)n_in;
    const float* slots_in = (const float*)d_in[0];
    const float* inputs   = (const float*)d_in[1];
    const float* ln_in_s  = (const float*)d_in[2];
    const float* ln_in_b  = (const float*)d_in[3];
    const float* Wk       = (const float*)d_in[4];
    const float* Wv       = (const float*)d_in[5];
    const float* Wp       = (const float*)d_in[6];
    const float* ge_ln_s  = (const float*)d_in[7];
    const float* ge_ln_b  = (const float*)d_in[8];
    const float* ge_W1    = (const float*)d_in[9];
    const float* ge_b1    = (const float*)d_in[10];
    const float* ge_W2    = (const float*)d_in[11];
    const float* ge_b2    = (const float*)d_in[12];
    const float* lnq_s    = (const float*)d_in[13];
    const float* lnq_b    = (const float*)d_in[14];
    const float* Wq       = (const float*)d_in[15];
    const float* Wo       = (const float*)d_in[16];
    const float* gru_Wi   = (const float*)d_in[17];
    const float* gru_bi   = (const float*)d_in[18];
    const float* gru_Wh   = (const float*)d_in[19];
    const float* gru_bhn  = (const float*)d_in[20];
    const float* mlp_ln_s = (const float*)d_in[21];
    const float* mlp_ln_b = (const float*)d_in[22];
    const float* mlp_W1   = (const float*)d_in[23];
    const float* mlp_b1   = (const float*)d_in[24];
    const float* mlp_W2   = (const float*)d_in[25];
    const float* mlp_b2   = (const float*)d_in[26];

    float *x, *pre, *kvb, *wkv, *wog, *slots, *sn, *q, *part, *psum;
    float *upd, *gi, *gh, *mlp1;
    cudaGetSymbolAddress((void**)&x,      g_x);
    cudaGetSymbolAddress((void**)&pre,    g_pre);
    cudaGetSymbolAddress((void**)&kvb,    g_kv);
    cudaGetSymbolAddress((void**)&wkv,    g_wkv);
    cudaGetSymbolAddress((void**)&wog,    g_wog);
    cudaGetSymbolAddress((void**)&slots,  g_slots);
    cudaGetSymbolAddress((void**)&sn,     g_sn);
    cudaGetSymbolAddress((void**)&q,      g_q);
    cudaGetSymbolAddress((void**)&part,   g_part);
    cudaGetSymbolAddress((void**)&psum,   g_psum);
    cudaGetSymbolAddress((void**)&upd,    g_upd);
    cudaGetSymbolAddress((void**)&gi,     g_gi);
    cudaGetSymbolAddress((void**)&gh,     g_gh);
    cudaGetSymbolAddress((void**)&mlp1,   g_mlp1);

    cudaFuncSetAttribute(k_genc, cudaFuncAttributeMaxDynamicSharedMemorySize,
                         GENC_SMEM_BYTES);

    // ---- setup ----
    k_copy<<<(CBS*CD + 255) / 256, 256>>>(slots_in, slots, CBS*CD);
    k_build_wkv<<<(CD*512 + 255) / 256, 256>>>(Wk, Wv, wkv);
    // Wog = Wo(256x256) @ gru_Wi(256x768)
    k_small<0><<<dim3(768/64, 256/64), 256>>>(Wo, gru_Wi, wog, 256, 768, 256,
                                              nullptr, nullptr, 1.f);
    k_lnrow<<<CT/8, 256>>>(inputs, 258, ln_in_s, ln_in_b, x);

    // pre = LN_ge( x @ [Wk|Wv] + positional )   (tf32 tensor cores)
    k_kvpre<<<dim3(4, 1024), 256>>>(x, wkv, pre, inputs, Wp, ge_ln_s, ge_ln_b);
    // kv = grid_enc MLP(pre)
    k_genc<<<CV8 / 128, 256, GENC_SMEM_BYTES>>>(pre, ge_W1, ge_b1, ge_W2, ge_b2, kvb);

    // ---- iterations ----
    for (int it = 0; it < 3; it++) {
        k_lnrow<<<CBS/8, 256>>>(slots, 256, lnq_s, lnq_b, sn);
        k_small<3><<<dim3(256/64, CBS/64), 256>>>(sn, Wq, q, CBS, 256, 256,
                                                  nullptr, nullptr, 0.125f);
        k_attn<<<dim3(8, CB*CH), 256>>>(q, kvb, part, psum);
        k_attnred<<<CBS, 256>>>(part, psum, upd);

        k_small<1><<<dim3(768/64, CBS/64), 256>>>(upd, wog, gi, CBS, 768, 256,
                                                  gru_bi, nullptr, 1.f);
        k_small<0><<<dim3(768/64, CBS/64), 256>>>(slots, gru_Wh, gh, CBS, 768, 256,
                                                  nullptr, nullptr, 1.f);
        k_gru<<<CBS, 256>>>(gi, gh, gru_bhn, slots);

        k_lnrow<<<CBS/8, 256>>>(slots, 256, mlp_ln_s, mlp_ln_b, sn);
        k_small<2><<<dim3(1024/64, CBS/64), 256>>>(sn, mlp_W1, mlp1, CBS, 1024, 256,
                                                   mlp_b1, nullptr, 1.f);
        k_small<4><<<dim3(256/64, CBS/64), 256>>>(mlp1, mlp_W2, slots, CBS, 256, 1024,
                                                  mlp_b2, slots, 1.f);
    }

    k_copy<<<(CBS*CD + 255) / 256, 256>>>(slots, (float*)d_out, CBS*CD);
    (void)out_size;
}